// round 6
// baseline (speedup 1.0000x reference)
#include <cuda_runtime.h>
#include <math.h>

#define Nn 50000
#define Ee 640000
#define Dd 128
#define Hh 8
#define DHd 16
#define FFd 256
#define Cc 5
#define Ll 6
#define EPSf 1e-5f

#define SCAN_B 1024
#define SCAN_NB ((Nn + SCAN_B - 1) / SCAN_B)  // 49

// ---------------- scratch (device globals; no allocs allowed) ----------------
__device__ float g_q[Nn * Dd];
__device__ float g_k[Nn * Dd];
__device__ float g_v[Nn * Dd];
__device__ float g_attn[Nn * Dd];
__device__ float g_tmp1[Nn * Dd];
__device__ float g_tmp2[Nn * Dd];
__device__ float g_ff[Nn * FFd];
__device__ double g_sum1[Dd];
__device__ double g_sq1[Dd];
__device__ double g_sum2[Dd];
__device__ double g_sq2[Dd];
// CSR
__device__ int g_deg[Nn];
__device__ int g_cursor[Nn];
__device__ int g_rowptr[Nn + 1];
__device__ int g_scan[Nn];
__device__ int g_bsum[SCAN_NB];
__device__ int g_col[Ee];

// packed fp32x2 FMA (Blackwell FFMA2, PTX-only)
__device__ __forceinline__ void fma2(unsigned long long& d, unsigned long long a,
                                     unsigned long long b) {
    asm("fma.rn.f32x2 %0, %1, %2, %0;" : "+l"(d) : "l"(a), "l"(b));
}
__device__ __forceinline__ unsigned long long pack2(float v) {
    unsigned long long r;
    asm("mov.b64 %0, {%1, %1};" : "=l"(r) : "f"(v));
    return r;
}

// ---------------- CSR build ----------------
__global__ void csr_zero_kernel() {
    int i = blockIdx.x * blockDim.x + threadIdx.x;
    if (i < Nn) {
        g_deg[i] = 0;
        g_cursor[i] = 0;
    }
}

__global__ void csr_hist_kernel(const int* __restrict__ ei) {
    int e = blockIdx.x * blockDim.x + threadIdx.x;
    if (e < Ee) atomicAdd(&g_deg[ei[Ee + e]], 1);
}

__global__ void csr_scan1_kernel() {
    __shared__ int sh[SCAN_B];
    int gi = blockIdx.x * SCAN_B + threadIdx.x;
    int v = (gi < Nn) ? g_deg[gi] : 0;
    sh[threadIdx.x] = v;
    __syncthreads();
#pragma unroll
    for (int off = 1; off < SCAN_B; off <<= 1) {
        int t = (threadIdx.x >= off) ? sh[threadIdx.x - off] : 0;
        __syncthreads();
        sh[threadIdx.x] += t;
        __syncthreads();
    }
    if (gi < Nn) g_scan[gi] = sh[threadIdx.x];
    if (threadIdx.x == SCAN_B - 1) g_bsum[blockIdx.x] = sh[threadIdx.x];
}

__global__ void csr_scan23_kernel() {
    __shared__ int soff;
    if (threadIdx.x == 0) {
        int acc = 0;
        for (int i = 0; i < (int)blockIdx.x; i++) acc += g_bsum[i];
        soff = acc;
    }
    __syncthreads();
    int gi = blockIdx.x * SCAN_B + threadIdx.x;
    if (gi < Nn) g_rowptr[gi + 1] = g_scan[gi] + soff;
    if (gi == 0) g_rowptr[0] = 0;
}

__global__ void csr_scatter_kernel(const int* __restrict__ ei) {
    int e = blockIdx.x * blockDim.x + threadIdx.x;
    if (e >= Ee) return;
    int src = ei[e], dst = ei[Ee + e];
    int pos = g_rowptr[dst] + atomicAdd(&g_cursor[dst], 1);
    g_col[pos] = src;
}

// ---------------- stats zero ----------------
__global__ void zero_stats_kernel(double* __restrict__ a, double* __restrict__ b) {
    int t = threadIdx.x;
    if (t < Dd) {
        a[t] = 0.0;
        b[t] = 0.0;
    }
}

// ---------------- fused GEMM ----------------
// Register-staged double-buffered pipeline:
//   LDG(next)->regs | compute(cur) | STS(regs->1-cur) | sync | flip
template <int K, int NC, bool BIAS, bool RELU, bool RES, bool BNA, bool BNRES,
          bool STATS, int NMAT>
__global__ __launch_bounds__(256, 2) void gemm_kernel(
    const float* __restrict__ A,
    const float* __restrict__ B0, const float* __restrict__ B1, const float* __restrict__ B2,
    const float* __restrict__ bias, const float* __restrict__ res,
    const float* __restrict__ bng, const float* __restrict__ bnb,
    const double* __restrict__ bnsum, const double* __restrict__ bnsq,
    double* __restrict__ stsum, double* __restrict__ stsq,
    float* __restrict__ C0, float* __restrict__ C1, float* __restrict__ C2) {
    const int BM = 128, BN = 128, BK = 16;
    const int YPM = NC / BN;
    constexpr int PSZ = BNA ? K : (BNRES ? NC : 1);
    constexpr int SSZ = STATS ? BN : 1;

    __shared__ __align__(16) float Ast[2][BK][BM + 4];
    __shared__ __align__(16) float Bs[2][BK][BN + 4];  // permuted layout
    __shared__ float s_sc[PSZ], s_sh[PSZ];
    __shared__ float s_cs[SSZ], s_cq[SSZ];

    int tid = threadIdx.x;
    int tx = tid & 15;
    int ty = tid >> 4;
    int rowBase = blockIdx.x * BM;
    int mat = (NMAT > 1) ? (blockIdx.y / YPM) : 0;
    int colBase = (blockIdx.y % YPM) * BN;
    const float* B = (NMAT > 1) ? (mat == 0 ? B0 : (mat == 1 ? B1 : B2)) : B0;
    float* C = (NMAT > 1) ? (mat == 0 ? C0 : (mat == 1 ? C1 : C2)) : C0;

    if (BNA || BNRES) {
        for (int c = tid; c < PSZ; c += 256) {
            double m = bnsum[c] / (double)Nn;
            double var = bnsq[c] / (double)Nn - m * m;
            float sc = rsqrtf((float)var + EPSf) * bng[c];
            s_sc[c] = sc;
            s_sh[c] = bnb[c] - (float)m * sc;
        }
        __syncthreads();
    }

    unsigned long long acc[8][4];
#pragma unroll
    for (int i = 0; i < 8; i++)
#pragma unroll
        for (int j = 0; j < 4; j++) acc[i][j] = 0ULL;

    // per-thread load indices (constant across tiles)
    const int ar0 = tid >> 2;                 // A row (l=0), +64 for l=1
    const int ac0 = (tid & 3) * 4;            // A col
    const int br0 = tid >> 5;                 // B row (l=0), +8 for l=1
    const int pch = tid & 31;                 // physical chunk
    const int bc0 = (pch < 16) ? (2 * pch) : (2 * (pch - 16) + 1);  // logical chunk

    float4 aReg[2], bReg[2];

    auto load_regs = [&](int kt) {
#pragma unroll
        for (int l = 0; l < 2; l++) {
            int grow = rowBase + ar0 + l * 64;
            aReg[l] = make_float4(0.f, 0.f, 0.f, 0.f);
            if (grow < Nn) aReg[l] = *(const float4*)&A[grow * K + kt + ac0];
        }
#pragma unroll
        for (int l = 0; l < 2; l++) {
            bReg[l] = *(const float4*)&B[(kt + br0 + l * 8) * NC + colBase + bc0 * 4];
        }
    };

    auto store_smem = [&](int kt, int buf) {
#pragma unroll
        for (int l = 0; l < 2; l++) {
            float4 av = aReg[l];
            if (BNA) {
                av.x = av.x * s_sc[kt + ac0 + 0] + s_sh[kt + ac0 + 0];
                av.y = av.y * s_sc[kt + ac0 + 1] + s_sh[kt + ac0 + 1];
                av.z = av.z * s_sc[kt + ac0 + 2] + s_sh[kt + ac0 + 2];
                av.w = av.w * s_sc[kt + ac0 + 3] + s_sh[kt + ac0 + 3];
            }
            int ar = ar0 + l * 64;
            Ast[buf][ac0 + 0][ar] = av.x;
            Ast[buf][ac0 + 1][ar] = av.y;
            Ast[buf][ac0 + 2][ar] = av.z;
            Ast[buf][ac0 + 3][ar] = av.w;
        }
#pragma unroll
        for (int l = 0; l < 2; l++) {
            *(float4*)&Bs[buf][br0 + l * 8][pch * 4] = bReg[l];
        }
    };

    // prologue
    load_regs(0);
    store_smem(0, 0);
    __syncthreads();
    int cur = 0;

    for (int kt = 0; kt < K; kt += BK) {
        bool hasNext = (kt + BK) < K;
        if (hasNext) load_regs(kt + BK);  // LDG in flight during compute
#pragma unroll
        for (int kk = 0; kk < BK; kk++) {
            float4 a0 = *(const float4*)&Ast[cur][kk][ty * 8];
            float4 a1 = *(const float4*)&Ast[cur][kk][ty * 8 + 4];
            ulonglong2 bA = *(const ulonglong2*)&Bs[cur][kk][tx * 4];
            ulonglong2 bB = *(const ulonglong2*)&Bs[cur][kk][64 + tx * 4];
            float a8[8] = {a0.x, a0.y, a0.z, a0.w, a1.x, a1.y, a1.z, a1.w};
            unsigned long long bb[4] = {bA.x, bA.y, bB.x, bB.y};
            unsigned long long ap[8];
#pragma unroll
            for (int i = 0; i < 8; i++) ap[i] = pack2(a8[i]);
#pragma unroll
            for (int i = 0; i < 8; i++)
#pragma unroll
                for (int j = 0; j < 4; j++) fma2(acc[i][j], ap[i], bb[j]);
        }
        if (hasNext) {
            store_smem(kt + BK, 1 - cur);  // waits on LDG here, post-compute
            __syncthreads();
            cur ^= 1;
        }
    }

    // ---------------- epilogue ----------------
    if (STATS) {
        __syncthreads();
        for (int c = tid; c < SSZ; c += 256) {
            s_cs[c] = 0.f;
            s_cq[c] = 0.f;
        }
        __syncthreads();
    }

    int col = colBase + tx * 8;
    float b8[8] = {0.f, 0.f, 0.f, 0.f, 0.f, 0.f, 0.f, 0.f};
    if (BIAS) {
        float4 ba = *(const float4*)&bias[col];
        float4 bb = *(const float4*)&bias[col + 4];
        b8[0] = ba.x; b8[1] = ba.y; b8[2] = ba.z; b8[3] = ba.w;
        b8[4] = bb.x; b8[5] = bb.y; b8[6] = bb.z; b8[7] = bb.w;
    }
    float scR[8], shR[8];
    if (BNRES) {
#pragma unroll
        for (int j = 0; j < 8; j++) {
            scR[j] = s_sc[col + j];
            shR[j] = s_sh[col + j];
        }
    }

    float ps[8] = {0.f, 0.f, 0.f, 0.f, 0.f, 0.f, 0.f, 0.f};
    float qs[8] = {0.f, 0.f, 0.f, 0.f, 0.f, 0.f, 0.f, 0.f};

#pragma unroll
    for (int i = 0; i < 8; i++) {
        int row = rowBase + ty * 8 + i;
        if (row >= Nn) continue;
        float r8[8] = {0.f, 0.f, 0.f, 0.f, 0.f, 0.f, 0.f, 0.f};
        if (RES) {
            float4 ra = *(const float4*)&res[row * NC + col];
            float4 rb = *(const float4*)&res[row * NC + col + 4];
            r8[0] = ra.x; r8[1] = ra.y; r8[2] = ra.z; r8[3] = ra.w;
            r8[4] = rb.x; r8[5] = rb.y; r8[6] = rb.z; r8[7] = rb.w;
            if (BNRES) {
#pragma unroll
                for (int j = 0; j < 8; j++) r8[j] = r8[j] * scR[j] + shR[j];
            }
        }
        float o[8];
#pragma unroll
        for (int j = 0; j < 4; j++) {
            float2 p = *(float2*)&acc[i][j];
            o[2 * j] = p.x;
            o[2 * j + 1] = p.y;
        }
#pragma unroll
        for (int j = 0; j < 8; j++) {
            float vv = o[j];
            if (BIAS) vv += b8[j];
            if (RES) vv += r8[j];
            if (RELU) vv = vv > 0.f ? vv : 0.f;
            o[j] = vv;
            if (STATS) {
                ps[j] += vv;
                qs[j] += vv * vv;
            }
        }
        *(float4*)&C[row * NC + col] = make_float4(o[0], o[1], o[2], o[3]);
        *(float4*)&C[row * NC + col + 4] = make_float4(o[4], o[5], o[6], o[7]);
    }

    if (STATS) {
#pragma unroll
        for (int j = 0; j < 8; j++) {
            atomicAdd(&s_cs[tx * 8 + j], ps[j]);
            atomicAdd(&s_cq[tx * 8 + j], qs[j]);
        }
        __syncthreads();
        for (int c = tid; c < SSZ; c += 256) {
            atomicAdd(&stsum[colBase + c], (double)s_cs[c]);
            atomicAdd(&stsq[colBase + c], (double)s_cq[c]);
        }
    }
}

// ---------------- fused edge attention: one warp per dst node ----------------
__global__ void attn_fused_kernel() {
    int warp = blockIdx.x * (blockDim.x >> 5) + (threadIdx.x >> 5);
    int lane = threadIdx.x & 31;
    if (warp >= Nn) return;
    int dst = warp;

    float4 q4 = *(const float4*)&g_q[dst * Dd + lane * 4];

    float m = -INFINITY;
    float l = 0.0f;
    float4 acc = make_float4(0.f, 0.f, 0.f, 0.f);

    int beg = g_rowptr[dst];
    int end = g_rowptr[dst + 1];
    for (int j = beg; j < end; j++) {
        int src = g_col[j];
        float4 k4 = *(const float4*)&g_k[src * Dd + lane * 4];
        float p = q4.x * k4.x + q4.y * k4.y + q4.z * k4.z + q4.w * k4.w;
        p += __shfl_xor_sync(0xffffffffu, p, 1);
        p += __shfl_xor_sync(0xffffffffu, p, 2);
        float s = p * 0.25f;

        float newm = fmaxf(m, s);
        float corr = __expf(m - newm);
        float pe = __expf(s - newm);
        float4 v4 = *(const float4*)&g_v[src * Dd + lane * 4];
        acc.x = acc.x * corr + pe * v4.x;
        acc.y = acc.y * corr + pe * v4.y;
        acc.z = acc.z * corr + pe * v4.z;
        acc.w = acc.w * corr + pe * v4.w;
        l = l * corr + pe;
        m = newm;
    }
    float inv = (l > 0.f) ? (1.0f / l) : 0.0f;
    acc.x *= inv; acc.y *= inv; acc.z *= inv; acc.w *= inv;
    *(float4*)&g_attn[dst * Dd + lane * 4] = acc;
}

// ---------------- final projection (with fused BN on input) ----------------
__global__ void proj_kernel(const float* __restrict__ Wp, const float* __restrict__ bp,
                            const float* __restrict__ bng, const float* __restrict__ bnb,
                            float* __restrict__ out) {
    int warp = blockIdx.x * (blockDim.x >> 5) + (threadIdx.x >> 5);
    int lane = threadIdx.x & 31;
    if (warp >= Nn) return;

    float sc[4], sh[4];
#pragma unroll
    for (int i = 0; i < 4; i++) {
        int c = lane + 32 * i;
        double m = g_sum2[c] / (double)Nn;
        double var = g_sq2[c] / (double)Nn - m * m;
        float s = rsqrtf((float)var + EPSf) * bng[c];
        sc[i] = s;
        sh[i] = bnb[c] - (float)m * s;
    }

    float acc[Cc] = {0.f, 0.f, 0.f, 0.f, 0.f};
#pragma unroll
    for (int i = 0; i < 4; i++) {
        int k = lane + 32 * i;
        float xv = g_tmp2[warp * Dd + k] * sc[i] + sh[i];
#pragma unroll
        for (int c = 0; c < Cc; c++) acc[c] += xv * Wp[k * Cc + c];
    }
#pragma unroll
    for (int c = 0; c < Cc; c++) {
#pragma unroll
        for (int o = 16; o > 0; o >>= 1) acc[c] += __shfl_down_sync(0xffffffffu, acc[c], o);
    }
    if (lane == 0) {
#pragma unroll
        for (int c = 0; c < Cc; c++) out[warp * Cc + c] = acc[c] + bp[c];
    }
}

// ---------------- launch ----------------
extern "C" void kernel_launch(void* const* d_in, const int* in_sizes, int n_in,
                              void* d_out, int out_size) {
    const float* x   = (const float*)d_in[0];
    const int*   ei  = (const int*)d_in[1];
    const float* Wq  = (const float*)d_in[2];
    const float* Wk  = (const float*)d_in[3];
    const float* Wv  = (const float*)d_in[4];
    const float* Wo  = (const float*)d_in[5];
    const float* g1  = (const float*)d_in[6];
    const float* bn1 = (const float*)d_in[7];
    const float* W1  = (const float*)d_in[8];
    const float* bf1 = (const float*)d_in[9];
    const float* W2  = (const float*)d_in[10];
    const float* bf2 = (const float*)d_in[11];
    const float* g2  = (const float*)d_in[12];
    const float* bn2 = (const float*)d_in[13];
    const float* Wp  = (const float*)d_in[14];
    const float* bp  = (const float*)d_in[15];
    float* out = (float*)d_out;

    float *pq, *pk, *pv, *pattn, *ptmp1, *ptmp2, *pff;
    double *psum1, *psq1, *psum2, *psq2;
    cudaGetSymbolAddress((void**)&pq, g_q);
    cudaGetSymbolAddress((void**)&pk, g_k);
    cudaGetSymbolAddress((void**)&pv, g_v);
    cudaGetSymbolAddress((void**)&pattn, g_attn);
    cudaGetSymbolAddress((void**)&ptmp1, g_tmp1);
    cudaGetSymbolAddress((void**)&ptmp2, g_tmp2);
    cudaGetSymbolAddress((void**)&pff, g_ff);
    cudaGetSymbolAddress((void**)&psum1, g_sum1);
    cudaGetSymbolAddress((void**)&psq1, g_sq1);
    cudaGetSymbolAddress((void**)&psum2, g_sum2);
    cudaGetSymbolAddress((void**)&psq2, g_sq2);

    const int gemmRows = (Nn + 127) / 128;  // 391
    const int edgeBlocks = (Ee + 255) / 256;
    const int nodeBlocks = (Nn + 255) / 256;
    const int warpBlocks = (Nn + 7) / 8;

    csr_zero_kernel<<<nodeBlocks, 256>>>();
    csr_hist_kernel<<<edgeBlocks, 256>>>(ei);
    csr_scan1_kernel<<<SCAN_NB, SCAN_B>>>();
    // #4: layer-0 QKV (profiled launch)
    gemm_kernel<Dd, Dd, false, false, false, false, false, false, 3>
        <<<dim3(gemmRows, 3), 256>>>(x, Wq, Wk, Wv, nullptr, nullptr,
                                     nullptr, nullptr, nullptr, nullptr,
                                     nullptr, nullptr, pq, pk, pv);
    csr_scan23_kernel<<<SCAN_NB, SCAN_B>>>();
    csr_scatter_kernel<<<edgeBlocks, 256>>>(ei);

    for (int i = 0; i < Ll; i++) {
        const float* wq = Wq + (size_t)i * Dd * Dd;
        const float* wk = Wk + (size_t)i * Dd * Dd;
        const float* wv = Wv + (size_t)i * Dd * Dd;
        const float* wo = Wo + (size_t)i * Dd * Dd;
        const float* w1 = W1 + (size_t)i * Dd * FFd;
        const float* w2 = W2 + (size_t)i * FFd * Dd;

        if (i > 0) {
            gemm_kernel<Dd, Dd, false, false, false, true, false, false, 3>
                <<<dim3(gemmRows, 3), 256>>>(ptmp2, wq, wk, wv, nullptr, nullptr,
                                             g2 + (i - 1) * Dd, bn2 + (i - 1) * Dd,
                                             psum2, psq2, nullptr, nullptr,
                                             pq, pk, pv);
        }

        attn_fused_kernel<<<warpBlocks, 256>>>();

        zero_stats_kernel<<<1, 128>>>(psum1, psq1);

        if (i == 0) {
            gemm_kernel<Dd, Dd, false, false, true, false, false, true, 1>
                <<<dim3(gemmRows, 1), 256>>>(pattn, wo, nullptr, nullptr,
                                             nullptr, x, nullptr, nullptr,
                                             nullptr, nullptr, psum1, psq1,
                                             ptmp1, nullptr, nullptr);
        } else {
            gemm_kernel<Dd, Dd, false, false, true, false, true, true, 1>
                <<<dim3(gemmRows, 1), 256>>>(pattn, wo, nullptr, nullptr,
                                             nullptr, ptmp2,
                                             g2 + (i - 1) * Dd, bn2 + (i - 1) * Dd,
                                             psum2, psq2, psum1, psq1,
                                             ptmp1, nullptr, nullptr);
        }

        gemm_kernel<Dd, FFd, true, true, false, true, false, false, 1>
            <<<dim3(gemmRows, 2), 256>>>(ptmp1, w1, nullptr, nullptr,
                                         bf1 + i * FFd, nullptr,
                                         g1 + i * Dd, bn1 + i * Dd,
                                         psum1, psq1, nullptr, nullptr,
                                         pff, nullptr, nullptr);

        zero_stats_kernel<<<1, 128>>>(psum2, psq2);

        gemm_kernel<FFd, Dd, true, false, true, false, true, true, 1>
            <<<dim3(gemmRows, 1), 256>>>(pff, w2, nullptr, nullptr,
                                         bf2 + i * Dd, ptmp1,
                                         g1 + i * Dd, bn1 + i * Dd,
                                         psum1, psq1, psum2, psq2,
                                         ptmp2, nullptr, nullptr);
    }

    proj_kernel<<<warpBlocks, 256>>>(Wp, bp, g2 + (Ll - 1) * Dd, bn2 + (Ll - 1) * Dd, out);
}